// round 16
// baseline (speedup 1.0000x reference)
#include <cuda_runtime.h>
#include <math.h>
#include <float.h>

// Shapes fixed by reference setup_inputs
#define N_PTS    16384
#define NQ_TOT   32768            // 2 sets * 16384 queries

// Grid for exact KNN
#define GR       64
#define NCELLS   (GR * GR * GR)   // 262144
#define CS       0.25f
#define INV_CS   4.0f
#define GORG     (-8.0f)

// Shell offset table: rings 0..RMAX over a (2*RMAX+1)^3 box
#define RMAX     24
#define BSIDE    (2 * RMAX + 1)   // 49
#define BOX      (BSIDE * BSIDE * BSIDE)  // 117649

#define KNN_TPB  256              // 8 warps/block, warp per query
#define KNN_BLKS (NQ_TOT / (KNN_TPB / 32))   // 4096

#define LOSS_TPB 256
#define LOSS_BLK (NQ_TOT / LOSS_TPB)         // 128

#define SDF_W      7000.0f
#define EIK_W      600.0f
#define ORI_W      500.0f
#define NEAR_ORI_W 10.0f
#define GRADN_W    200.0f

// Scratch (fully rewritten every launch)
__device__ int    g_count[NCELLS];
__device__ int    g_start[NCELLS + 1];
__device__ int    g_cursor[NCELLS];
__device__ float4 g_sorted[N_PTS];     // (x, y, z, bits(orig_idx)) cell-sorted
__device__ int    g_shell[BOX];        // packed (dx+32)|(dy+32)<<8|(dz+32)<<16, ring-ordered
__device__ int    g_ringcur[RMAX + 1];
__device__ int2   g_nn[NQ_TOT];        // top-2 original indices per query
__device__ float4 g_partA[LOSS_BLK];   // (ori, nori, sdf, eik)
__device__ float  g_partB[LOSS_BLK];   // gradn

__device__ __forceinline__ int cell_coord(float v) {
    int c = (int)floorf((v - GORG) * INV_CS);
    return min(max(c, 0), GR - 1);
}

__device__ __forceinline__ int ring_base(int r) {   // cells with cheb < r
    if (r == 0) return 0;
    int s = 2 * r - 1;
    return s * s * s;
}

// value-then-index ordering: deterministic regardless of scan order
__device__ __forceinline__ bool lessvi(float v, int i, float w, int j) {
    return (v < w) | ((v == w) & (i < j));
}

#define INS_TOP2(d2, pidx)                                          \
    do {                                                            \
        if (lessvi(d2, pidx, b2, i2)) {                             \
            if (lessvi(d2, pidx, b1, i1)) {                         \
                b2 = b1; i2 = i1; b1 = d2; i1 = pidx;               \
            } else { b2 = d2; i2 = pidx; }                          \
        }                                                           \
    } while (0)

// ---------------- build kernels ----------------

__global__ __launch_bounds__(256) void zero_kernel() {
    int i = blockIdx.x * 256 + threadIdx.x;
    if (i < NCELLS) g_count[i] = 0;
    if (i <= RMAX)  g_ringcur[i] = 0;
}

__global__ __launch_bounds__(256) void build_shell_kernel() {
    int idx = blockIdx.x * 256 + threadIdx.x;
    if (idx >= BOX) return;
    int dz = idx / (BSIDE * BSIDE) - RMAX;
    int rem = idx % (BSIDE * BSIDE);
    int dy = rem / BSIDE - RMAX;
    int dx = rem % BSIDE - RMAX;
    int r = max(abs(dx), max(abs(dy), abs(dz)));
    int pos = atomicAdd(&g_ringcur[r], 1);
    g_shell[ring_base(r) + pos] = (dx + 32) | ((dy + 32) << 8) | ((dz + 32) << 16);
}

__global__ __launch_bounds__(256) void count_kernel(const float* __restrict__ surface) {
    int p = blockIdx.x * 256 + threadIdx.x;
    if (p >= N_PTS) return;
    int cx = cell_coord(surface[3*p+0]);
    int cy = cell_coord(surface[3*p+1]);
    int cz = cell_coord(surface[3*p+2]);
    atomicAdd(&g_count[(cz * GR + cy) * GR + cx], 1);
}

__global__ __launch_bounds__(1024) void scan_kernel() {
    __shared__ int sh[1024];
    const int t = threadIdx.x;
    const int cpt = NCELLS / 1024;          // 256 cells per thread
    const int base = t * cpt;
    int s = 0;
    for (int i = 0; i < cpt; ++i) s += g_count[base + i];
    sh[t] = s;
    __syncthreads();
    for (int off = 1; off < 1024; off <<= 1) {
        int v = (t >= off) ? sh[t - off] : 0;
        __syncthreads();
        sh[t] += v;
        __syncthreads();
    }
    int run = (t == 0) ? 0 : sh[t - 1];
    for (int i = 0; i < cpt; ++i) {
        g_start[base + i]  = run;
        g_cursor[base + i] = run;
        run += g_count[base + i];
    }
    if (t == 1023) g_start[NCELLS] = run;   // = N_PTS
}

__global__ __launch_bounds__(256) void scatter_kernel(const float* __restrict__ surface) {
    int p = blockIdx.x * 256 + threadIdx.x;
    if (p >= N_PTS) return;
    float x = surface[3*p+0], y = surface[3*p+1], z = surface[3*p+2];
    int cx = cell_coord(x), cy = cell_coord(y), cz = cell_coord(z);
    int pos = atomicAdd(&g_cursor[(cz * GR + cy) * GR + cx], 1);
    g_sorted[pos] = make_float4(x, y, z, __int_as_float(p));
}

// ---------------- KNN: warp per query, table-driven shells,
//                  hybrid lane-serial / warp-coop cell scan ----------------

__global__ __launch_bounds__(KNN_TPB) void grid_knn_kernel(
    const float* __restrict__ off_pts,
    const float* __restrict__ near_pts)
{
    const int lane = threadIdx.x & 31;
    const int slot = (blockIdx.x * KNN_TPB + threadIdx.x) >> 5;  // warp id = query slot
    const int set  = slot >> 14;
    const int qi   = slot & (N_PTS - 1);

    const float* __restrict__ qsrc = set ? near_pts : off_pts;
    const float qx = qsrc[3*qi+0];
    const float qy = qsrc[3*qi+1];
    const float qz = qsrc[3*qi+2];

    const int cx = cell_coord(qx), cy = cell_coord(qy), cz = cell_coord(qz);
    // L-inf overhang of q outside its (clamped) home cell box
    float bx0 = GORG + cx * CS, by0 = GORG + cy * CS, bz0 = GORG + cz * CS;
    float hx = fmaxf(fmaxf(bx0 - qx, qx - (bx0 + CS)), 0.0f);
    float hy = fmaxf(fmaxf(by0 - qy, qy - (by0 + CS)), 0.0f);
    float hz = fmaxf(fmaxf(bz0 - qz, qz - (bz0 + CS)), 0.0f);
    const float hinf = fmaxf(hx, fmaxf(hy, hz));

    float b1 = FLT_MAX, b2 = FLT_MAX;
    int   i1 = 0x7FFFFFFF, i2 = 0x7FFFFFFF;

    bool done = false;
    for (int r = 0; r <= RMAX; ++r) {
        const int base = ring_base(r);
        const int S    = ring_base(r + 1) - base;   // 24r^2+2 (1 for r=0)

        for (int bb = 0; bb < S; bb += 32) {
            const int t = bb + lane;
            int cs_ = 0, ce_ = 0;
            if (t < S) {
                int packed = g_shell[base + t];
                int dx = (packed & 255) - 32;
                int dy = ((packed >> 8) & 255) - 32;
                int dz = ((packed >> 16) & 255) - 32;
                int x = cx + dx, y = cy + dy, z = cz + dz;
                if ((unsigned)x < GR && (unsigned)y < GR && (unsigned)z < GR) {
                    int cell = (z * GR + y) * GR + x;
                    cs_ = g_start[cell];
                    ce_ = g_start[cell + 1];
                }
            }
            // phase 1: each lane scans up to 4 points of its own cell
            int lim = min(ce_, cs_ + 4);
            for (int i = cs_; i < lim; ++i) {
                float4 pv = g_sorted[i];
                float ddx = qx - pv.x, ddy = qy - pv.y, ddz = qz - pv.z;
                float d2 = ddx*ddx + ddy*ddy + ddz*ddz;
                int pidx = __float_as_int(pv.w);
                INS_TOP2(d2, pidx);
            }
            // phase 2: fat-cell remainders scanned warp-cooperatively
            unsigned mask = __ballot_sync(0xFFFFFFFFu, ce_ > cs_ + 4);
            while (mask) {
                int src = __ffs(mask) - 1;
                mask &= mask - 1;
                int s  = __shfl_sync(0xFFFFFFFFu, cs_, src) + 4;
                int e2 = __shfl_sync(0xFFFFFFFFu, ce_, src);
                for (int i = s + lane; i < e2; i += 32) {
                    float4 pv = g_sorted[i];
                    float ddx = qx - pv.x, ddy = qy - pv.y, ddz = qz - pv.z;
                    float d2 = ddx*ddx + ddy*ddy + ddz*ddz;
                    int pidx = __float_as_int(pv.w);
                    INS_TOP2(d2, pidx);
                }
            }
        }

        // safe stop: min over lanes of lane-b2 >= true warp-b2;
        // unscanned points have d >= r*CS - hinf
        float est = b2;
        #pragma unroll
        for (int off = 16; off; off >>= 1)
            est = fminf(est, __shfl_xor_sync(0xFFFFFFFFu, est, off));
        float bound = fmaxf((float)r * CS - hinf, 0.0f);
        if (est <= bound * bound) { done = true; break; }
    }

    if (!done) {
        // table exhausted without provable stop (≈ never): exact fallback,
        // fresh warp-coop scan of ALL points (reset avoids double-insert)
        b1 = FLT_MAX; b2 = FLT_MAX; i1 = 0x7FFFFFFF; i2 = 0x7FFFFFFF;
        for (int i = lane; i < N_PTS; i += 32) {
            float4 pv = g_sorted[i];
            float ddx = qx - pv.x, ddy = qy - pv.y, ddz = qz - pv.z;
            float d2 = ddx*ddx + ddy*ddy + ddz*ddz;
            int pidx = __float_as_int(pv.w);
            INS_TOP2(d2, pidx);
        }
    }

    // warp merge of sorted (b1,i1,b2,i2) pairs
    #pragma unroll
    for (int off = 16; off; off >>= 1) {
        float w1 = __shfl_xor_sync(0xFFFFFFFFu, b1, off);
        int   j1 = __shfl_xor_sync(0xFFFFFFFFu, i1, off);
        float w2 = __shfl_xor_sync(0xFFFFFFFFu, b2, off);
        int   j2 = __shfl_xor_sync(0xFFFFFFFFu, i2, off);
        if (lessvi(w1, j1, b1, i1)) {
            if (lessvi(b1, i1, w2, j2)) { b2 = b1; i2 = i1; }
            else                        { b2 = w2; i2 = j2; }
            b1 = w1; i1 = j1;
        } else {
            if (lessvi(w1, j1, b2, i2)) { b2 = w1; i2 = j1; }
        }
    }

    if (lane == 0) g_nn[slot] = make_int2(i1, i2);
}

// ---------------- loss epilogue ----------------

__global__ __launch_bounds__(LOSS_TPB) void loss_kernel(
    const float* __restrict__ manifold_pred,
    const float* __restrict__ manifold_grad,
    const float* __restrict__ nonmanifold_pred,
    const float* __restrict__ near_pred,
    const float* __restrict__ surface,
    const float* __restrict__ normals,
    const float* __restrict__ off_pts,
    const float* __restrict__ near_pts)
{
    __shared__ float4 rA[LOSS_TPB];
    __shared__ float  rB[LOSS_TPB];

    const int tid  = threadIdx.x;
    const int slot = blockIdx.x * LOSS_TPB + tid;

    int2 nn = g_nn[slot];
    const int j1 = nn.x, j2 = nn.y;

    const int set = slot >> 14;
    const int qi  = slot & (N_PTS - 1);
    const float* __restrict__ qsrc = set ? near_pts : off_pts;
    const float qx = qsrc[3*qi+0], qy = qsrc[3*qi+1], qz = qsrc[3*qi+2];

    float s1x = surface[3*j1+0], s1y = surface[3*j1+1], s1z = surface[3*j1+2];
    float n1x = normals[3*j1+0], n1y = normals[3*j1+1], n1z = normals[3*j1+2];
    float s2x = surface[3*j2+0], s2y = surface[3*j2+1], s2z = surface[3*j2+2];
    float n2x = normals[3*j2+0], n2y = normals[3*j2+1], n2z = normals[3*j2+2];

    float dot1 = (qx-s1x)*n1x + (qy-s1y)*n1y + (qz-s1z)*n1z;
    float dot2 = (qx-s2x)*n2x + (qy-s2y)*n2y + (qz-s2z)*n2z;
    float sd   = dot1 + dot2;
    float sgn  = (sd > 0.0f) ? 1.0f : ((sd < 0.0f) ? -1.0f : 0.0f);

    float pred    = set ? near_pred[qi] : nonmanifold_pred[qi];
    float contrib = fmaxf(-pred * sgn, 0.0f);
    float ori  = set ? 0.0f : contrib;
    float nori = set ? contrib : 0.0f;

    // small losses: set-0 slots cover elements 0..16383 exactly once
    float sdf_e = 0.0f, eik_e = 0.0f, gn_e = 0.0f;
    if (slot < N_PTS) {
        const int e = slot;
        float mp = manifold_pred[e];
        sdf_e = mp * mp;
        float gx = manifold_grad[3*e+0], gy = manifold_grad[3*e+1], gz = manifold_grad[3*e+2];
        float nxv = normals[3*e+0],      nyv = normals[3*e+1],      nzv = normals[3*e+2];
        float nrm = sqrtf(gx*gx + gy*gy + gz*gz) - 1.0f;
        eik_e = nrm * nrm;
        gn_e  = (gx-nxv)*(gx-nxv) + (gy-nyv)*(gy-nyv) + (gz-nzv)*(gz-nzv);
    }

    rA[tid] = make_float4(ori, nori, sdf_e, eik_e);
    rB[tid] = gn_e;
    __syncthreads();
    for (int s = LOSS_TPB / 2; s > 0; s >>= 1) {
        if (tid < s) {
            float4 a = rA[tid], c = rA[tid + s];
            rA[tid] = make_float4(a.x + c.x, a.y + c.y, a.z + c.z, a.w + c.w);
            rB[tid] += rB[tid + s];
        }
        __syncthreads();
    }
    if (tid == 0) { g_partA[blockIdx.x] = rA[0]; g_partB[blockIdx.x] = rB[0]; }
}

__global__ __launch_bounds__(LOSS_BLK) void finish_kernel(float* __restrict__ out)
{
    __shared__ float4 rA[LOSS_BLK];
    __shared__ float  rB[LOSS_BLK];
    const int t = threadIdx.x;
    rA[t] = g_partA[t];
    rB[t] = g_partB[t];
    __syncthreads();
    for (int s = LOSS_BLK / 2; s > 0; s >>= 1) {
        if (t < s) {
            float4 a = rA[t], c = rA[t + s];
            rA[t] = make_float4(a.x + c.x, a.y + c.y, a.z + c.z, a.w + c.w);
            rB[t] += rB[t + s];
        }
        __syncthreads();
    }
    if (t == 0) {
        const float inv = 1.0f / (float)N_PTS;
        float ori_loss  = rA[0].x * inv;
        float nori_loss = rA[0].y * inv;
        float sdf_loss  = rA[0].z * inv;
        float eik_loss  = rA[0].w * inv;
        float gn_loss   = rB[0] / (3.0f * (float)N_PTS);
        float total = SDF_W * sdf_loss + EIK_W * eik_loss + ORI_W * ori_loss
                    + NEAR_ORI_W * nori_loss + GRADN_W * gn_loss;
        out[0] = total;
        out[1] = sdf_loss;
        out[2] = eik_loss;
        out[3] = ori_loss;
        out[4] = nori_loss;
        out[5] = gn_loss;
    }
}

extern "C" void kernel_launch(void* const* d_in, const int* in_sizes, int n_in,
                              void* d_out, int out_size)
{
    const float* manifold_pred    = (const float*)d_in[0];
    const float* manifold_grad    = (const float*)d_in[1];
    const float* nonmanifold_pred = (const float*)d_in[2];
    const float* near_points_pred = (const float*)d_in[3];
    const float* surface_points   = (const float*)d_in[4];
    const float* surface_normals  = (const float*)d_in[5];
    const float* off_surface_pts  = (const float*)d_in[6];
    const float* near_points      = (const float*)d_in[7];
    float* out = (float*)d_out;

    zero_kernel       <<<NCELLS / 256, 256>>>();
    build_shell_kernel<<<(BOX + 255) / 256, 256>>>();
    count_kernel      <<<N_PTS / 256, 256>>>(surface_points);
    scan_kernel       <<<1, 1024>>>();
    scatter_kernel    <<<N_PTS / 256, 256>>>(surface_points);
    grid_knn_kernel   <<<KNN_BLKS, KNN_TPB>>>(off_surface_pts, near_points);
    loss_kernel       <<<LOSS_BLK, LOSS_TPB>>>(manifold_pred, manifold_grad,
                                               nonmanifold_pred, near_points_pred,
                                               surface_points, surface_normals,
                                               off_surface_pts, near_points);
    finish_kernel     <<<1, LOSS_BLK>>>(out);
}

// round 17
// speedup vs baseline: 7.1046x; 7.1046x over previous
#include <cuda_runtime.h>
#include <math.h>
#include <float.h>

// Shapes fixed by reference setup_inputs
#define N_PTS    16384
#define NQ_TOT   32768            // 2 sets * 16384 queries

// Grid for exact KNN
#define GR       32
#define NCELLS   (GR * GR * GR)   // 32768
#define CS       0.5f
#define INV_CS   2.0f
#define GORG     (-8.0f)

// Shell offset table: rings 0..RMAX, RMAX=31 covers whole grid from any cell
#define RMAX     31
#define BSIDE    (2 * RMAX + 1)   // 63
#define BOX      (BSIDE * BSIDE * BSIDE)  // 250047

#define KNN_TPB  256              // 8 warps/block, warp per query
#define KNN_BLKS (NQ_TOT / (KNN_TPB / 32))   // 4096

#define LOSS_TPB 256
#define LOSS_BLK (NQ_TOT / LOSS_TPB)         // 128

#define SDF_W      7000.0f
#define EIK_W      600.0f
#define ORI_W      500.0f
#define NEAR_ORI_W 10.0f
#define GRADN_W    200.0f

// Scratch (fully rewritten every launch)
__device__ int      g_count[NCELLS];
__device__ int      g_cinfo[NCELLS];     // (start << 9) | count  (count < 512)
__device__ int      g_cursor[NCELLS];
__device__ unsigned g_bitmask[NCELLS / 32];  // occupancy, 4KB
__device__ float4   g_sorted[N_PTS];     // (x, y, z, bits(orig_idx)) cell-sorted
__device__ int      g_shell[BOX];        // packed (dx+32)|(dy+32)<<8|(dz+32)<<16, ring-ordered
__device__ int2     g_nn[NQ_TOT];        // top-2 original indices per query
__device__ float4   g_partA[LOSS_BLK];   // (ori, nori, sdf, eik)
__device__ float    g_partB[LOSS_BLK];   // gradn

__device__ __forceinline__ int cell_coord(float v) {
    int c = (int)floorf((v - GORG) * INV_CS);
    return min(max(c, 0), GR - 1);
}

__device__ __forceinline__ int ring_base(int r) {   // #cells with cheb < r
    if (r == 0) return 0;
    int s = 2 * r - 1;
    return s * s * s;
}

// value-then-index ordering: deterministic regardless of scan order
__device__ __forceinline__ bool lessvi(float v, int i, float w, int j) {
    return (v < w) | ((v == w) & (i < j));
}

#define INS_TOP2(d2, pidx)                                          \
    do {                                                            \
        if (lessvi(d2, pidx, b2, i2)) {                             \
            if (lessvi(d2, pidx, b1, i1)) {                         \
                b2 = b1; i2 = i1; b1 = d2; i1 = pidx;               \
            } else { b2 = d2; i2 = pidx; }                          \
        }                                                           \
    } while (0)

// ---------------- build kernels ----------------

__global__ __launch_bounds__(256) void zero_kernel() {
    int i = blockIdx.x * 256 + threadIdx.x;
    if (i < NCELLS) g_count[i] = 0;
}

// Deterministic shell table: closed-form rank within each Chebyshev ring
__global__ __launch_bounds__(256) void build_shell_kernel() {
    int idx = blockIdx.x * 256 + threadIdx.x;
    if (idx >= BOX) return;
    int dz = idx / (BSIDE * BSIDE) - RMAX;
    int rem = idx % (BSIDE * BSIDE);
    int dy = rem / BSIDE - RMAX;
    int dx = rem % BSIDE - RMAX;
    int r = max(abs(dx), max(abs(dy), abs(dz)));
    int rank;
    if (r == 0) {
        rank = 0;
    } else {
        int side = 2 * r + 1;
        int capA = side * side;
        if (dz == -r)      rank = (dy + r) * side + (dx + r);
        else if (dz == r)  rank = capA + (dy + r) * side + (dx + r);
        else {
            int layer = dz + r - 1;          // 0 .. 2r-2
            int pos;
            if (dy == -r)      pos = dx + r;                 // 0..2r
            else if (dy == r)  pos = side + dx + r;
            else if (dx == -r) pos = 2 * side + (dy + r - 1);
            else               pos = 2 * side + (2 * r - 1) + (dy + r - 1);
            rank = 2 * capA + layer * 8 * r + pos;
        }
    }
    g_shell[ring_base(r) + rank] = (dx + 32) | ((dy + 32) << 8) | ((dz + 32) << 16);
}

__global__ __launch_bounds__(256) void count_kernel(const float* __restrict__ surface) {
    int p = blockIdx.x * 256 + threadIdx.x;
    if (p >= N_PTS) return;
    int cx = cell_coord(surface[3*p+0]);
    int cy = cell_coord(surface[3*p+1]);
    int cz = cell_coord(surface[3*p+2]);
    atomicAdd(&g_count[(cz * GR + cy) * GR + cx], 1);
}

// Vectorized single-block scan: 1024 threads x 32 cells; also emits packed
// cinfo, cursor copy, and one occupancy-bitmask word per thread.
__global__ __launch_bounds__(1024) void scan_kernel() {
    __shared__ int sh[1024];
    const int t = threadIdx.x;
    const int base = t * 32;

    int cnt[32];
    const int4* src = reinterpret_cast<const int4*>(g_count + base);
    #pragma unroll
    for (int v = 0; v < 8; ++v) {
        int4 q = src[v];
        cnt[4*v+0] = q.x; cnt[4*v+1] = q.y; cnt[4*v+2] = q.z; cnt[4*v+3] = q.w;
    }
    int s = 0;
    #pragma unroll
    for (int i = 0; i < 32; ++i) s += cnt[i];
    sh[t] = s;
    __syncthreads();
    for (int off = 1; off < 1024; off <<= 1) {
        int v = (t >= off) ? sh[t - off] : 0;
        __syncthreads();
        sh[t] += v;
        __syncthreads();
    }
    int run = (t == 0) ? 0 : sh[t - 1];
    unsigned bits = 0;
    #pragma unroll
    for (int i = 0; i < 32; ++i) {
        g_cinfo[base + i]  = (run << 9) | cnt[i];
        g_cursor[base + i] = run;
        if (cnt[i] > 0) bits |= (1u << i);
        run += cnt[i];
    }
    g_bitmask[t] = bits;
}

__global__ __launch_bounds__(256) void scatter_kernel(const float* __restrict__ surface) {
    int p = blockIdx.x * 256 + threadIdx.x;
    if (p >= N_PTS) return;
    float x = surface[3*p+0], y = surface[3*p+1], z = surface[3*p+2];
    int cx = cell_coord(x), cy = cell_coord(y), cz = cell_coord(z);
    int pos = atomicAdd(&g_cursor[(cz * GR + cy) * GR + cx], 1);
    g_sorted[pos] = make_float4(x, y, z, __int_as_float(p));
}

// ---------------- KNN: warp per query, table shells, smem occupancy bitmask,
//                  hybrid lane-serial / warp-coop cell scan ----------------

__global__ __launch_bounds__(KNN_TPB) void grid_knn_kernel(
    const float* __restrict__ off_pts,
    const float* __restrict__ near_pts)
{
    __shared__ unsigned sm_bits[NCELLS / 32];   // 4KB occupancy bitmask

    const int tid  = threadIdx.x;
    const int lane = tid & 31;
    for (int w = tid; w < NCELLS / 32; w += KNN_TPB) sm_bits[w] = g_bitmask[w];
    __syncthreads();

    const int slot = (blockIdx.x * KNN_TPB + tid) >> 5;   // warp id = query slot
    const int set  = slot >> 14;
    const int qi   = slot & (N_PTS - 1);

    const float* __restrict__ qsrc = set ? near_pts : off_pts;
    const float qx = qsrc[3*qi+0];
    const float qy = qsrc[3*qi+1];
    const float qz = qsrc[3*qi+2];

    const int cx = cell_coord(qx), cy = cell_coord(qy), cz = cell_coord(qz);
    // L-inf overhang of q outside its (clamped) home cell box
    float bx0 = GORG + cx * CS, by0 = GORG + cy * CS, bz0 = GORG + cz * CS;
    float hx = fmaxf(fmaxf(bx0 - qx, qx - (bx0 + CS)), 0.0f);
    float hy = fmaxf(fmaxf(by0 - qy, qy - (by0 + CS)), 0.0f);
    float hz = fmaxf(fmaxf(bz0 - qz, qz - (bz0 + CS)), 0.0f);
    const float hinf = fmaxf(hx, fmaxf(hy, hz));

    float b1 = FLT_MAX, b2 = FLT_MAX;
    int   i1 = 0x7FFFFFFF, i2 = 0x7FFFFFFF;

    for (int r = 0; r <= RMAX; ++r) {
        const int base = ring_base(r);
        const int S    = ring_base(r + 1) - base;   // 24r^2+2 (1 for r=0)

        for (int bb = 0; bb < S; bb += 32) {
            const int t = bb + lane;
            int cinfo = 0;
            if (t < S) {
                int packed = g_shell[base + t];
                int dx = (packed & 255) - 32;
                int dy = ((packed >> 8) & 255) - 32;
                int dz = ((packed >> 16) & 255) - 32;
                int x = cx + dx, y = cy + dy, z = cz + dz;
                if ((unsigned)x < GR && (unsigned)y < GR && (unsigned)z < GR) {
                    int cell = (z * GR + y) * GR + x;
                    // occupancy check in smem: no L2 touch for empty cells
                    if ((sm_bits[cell >> 5] >> (cell & 31)) & 1u)
                        cinfo = g_cinfo[cell];
                }
            }
            int cs_ = cinfo >> 9;
            int cnt = cinfo & 511;
            // phase 1: each lane scans up to 4 points of its own cell
            int lim = cs_ + min(cnt, 4);
            for (int i = cs_; i < lim; ++i) {
                float4 pv = g_sorted[i];
                float ddx = qx - pv.x, ddy = qy - pv.y, ddz = qz - pv.z;
                float d2 = ddx*ddx + ddy*ddy + ddz*ddz;
                int pidx = __float_as_int(pv.w);
                INS_TOP2(d2, pidx);
            }
            // phase 2: fat-cell remainders scanned warp-cooperatively
            unsigned mask = __ballot_sync(0xFFFFFFFFu, cnt > 4);
            while (mask) {
                int src = __ffs(mask) - 1;
                mask &= mask - 1;
                int s  = __shfl_sync(0xFFFFFFFFu, cs_, src) + 4;
                int e2 = __shfl_sync(0xFFFFFFFFu, cs_ + cnt, src);
                for (int i = s + lane; i < e2; i += 32) {
                    float4 pv = g_sorted[i];
                    float ddx = qx - pv.x, ddy = qy - pv.y, ddz = qz - pv.z;
                    float d2 = ddx*ddx + ddy*ddy + ddz*ddz;
                    int pidx = __float_as_int(pv.w);
                    INS_TOP2(d2, pidx);
                }
            }
        }

        // safe stop: min over lanes of lane-b2 >= true warp-b2;
        // unscanned points have d >= r*CS - hinf.  After r=RMAX the whole
        // grid has been scanned, so exiting without the stop is still exact.
        float est = b2;
        #pragma unroll
        for (int off = 16; off; off >>= 1)
            est = fminf(est, __shfl_xor_sync(0xFFFFFFFFu, est, off));
        float bound = fmaxf((float)r * CS - hinf, 0.0f);
        if (est <= bound * bound) break;
    }

    // warp merge of sorted (b1,i1,b2,i2) pairs
    #pragma unroll
    for (int off = 16; off; off >>= 1) {
        float w1 = __shfl_xor_sync(0xFFFFFFFFu, b1, off);
        int   j1 = __shfl_xor_sync(0xFFFFFFFFu, i1, off);
        float w2 = __shfl_xor_sync(0xFFFFFFFFu, b2, off);
        int   j2 = __shfl_xor_sync(0xFFFFFFFFu, i2, off);
        if (lessvi(w1, j1, b1, i1)) {
            if (lessvi(b1, i1, w2, j2)) { b2 = b1; i2 = i1; }
            else                        { b2 = w2; i2 = j2; }
            b1 = w1; i1 = j1;
        } else {
            if (lessvi(w1, j1, b2, i2)) { b2 = w1; i2 = j1; }
        }
    }

    if (lane == 0) g_nn[slot] = make_int2(i1, i2);
}

// ---------------- loss epilogue ----------------

__global__ __launch_bounds__(LOSS_TPB) void loss_kernel(
    const float* __restrict__ manifold_pred,
    const float* __restrict__ manifold_grad,
    const float* __restrict__ nonmanifold_pred,
    const float* __restrict__ near_pred,
    const float* __restrict__ surface,
    const float* __restrict__ normals,
    const float* __restrict__ off_pts,
    const float* __restrict__ near_pts)
{
    __shared__ float4 rA[LOSS_TPB];
    __shared__ float  rB[LOSS_TPB];

    const int tid  = threadIdx.x;
    const int slot = blockIdx.x * LOSS_TPB + tid;

    int2 nn = g_nn[slot];
    const int j1 = nn.x, j2 = nn.y;

    const int set = slot >> 14;
    const int qi  = slot & (N_PTS - 1);
    const float* __restrict__ qsrc = set ? near_pts : off_pts;
    const float qx = qsrc[3*qi+0], qy = qsrc[3*qi+1], qz = qsrc[3*qi+2];

    float s1x = surface[3*j1+0], s1y = surface[3*j1+1], s1z = surface[3*j1+2];
    float n1x = normals[3*j1+0], n1y = normals[3*j1+1], n1z = normals[3*j1+2];
    float s2x = surface[3*j2+0], s2y = surface[3*j2+1], s2z = surface[3*j2+2];
    float n2x = normals[3*j2+0], n2y = normals[3*j2+1], n2z = normals[3*j2+2];

    float dot1 = (qx-s1x)*n1x + (qy-s1y)*n1y + (qz-s1z)*n1z;
    float dot2 = (qx-s2x)*n2x + (qy-s2y)*n2y + (qz-s2z)*n2z;
    float sd   = dot1 + dot2;
    float sgn  = (sd > 0.0f) ? 1.0f : ((sd < 0.0f) ? -1.0f : 0.0f);

    float pred    = set ? near_pred[qi] : nonmanifold_pred[qi];
    float contrib = fmaxf(-pred * sgn, 0.0f);
    float ori  = set ? 0.0f : contrib;
    float nori = set ? contrib : 0.0f;

    // small losses: set-0 slots cover elements 0..16383 exactly once
    float sdf_e = 0.0f, eik_e = 0.0f, gn_e = 0.0f;
    if (slot < N_PTS) {
        const int e = slot;
        float mp = manifold_pred[e];
        sdf_e = mp * mp;
        float gx = manifold_grad[3*e+0], gy = manifold_grad[3*e+1], gz = manifold_grad[3*e+2];
        float nxv = normals[3*e+0],      nyv = normals[3*e+1],      nzv = normals[3*e+2];
        float nrm = sqrtf(gx*gx + gy*gy + gz*gz) - 1.0f;
        eik_e = nrm * nrm;
        gn_e  = (gx-nxv)*(gx-nxv) + (gy-nyv)*(gy-nyv) + (gz-nzv)*(gz-nzv);
    }

    rA[tid] = make_float4(ori, nori, sdf_e, eik_e);
    rB[tid] = gn_e;
    __syncthreads();
    for (int s = LOSS_TPB / 2; s > 0; s >>= 1) {
        if (tid < s) {
            float4 a = rA[tid], c = rA[tid + s];
            rA[tid] = make_float4(a.x + c.x, a.y + c.y, a.z + c.z, a.w + c.w);
            rB[tid] += rB[tid + s];
        }
        __syncthreads();
    }
    if (tid == 0) { g_partA[blockIdx.x] = rA[0]; g_partB[blockIdx.x] = rB[0]; }
}

__global__ __launch_bounds__(LOSS_BLK) void finish_kernel(float* __restrict__ out)
{
    __shared__ float4 rA[LOSS_BLK];
    __shared__ float  rB[LOSS_BLK];
    const int t = threadIdx.x;
    rA[t] = g_partA[t];
    rB[t] = g_partB[t];
    __syncthreads();
    for (int s = LOSS_BLK / 2; s > 0; s >>= 1) {
        if (t < s) {
            float4 a = rA[t], c = rA[t + s];
            rA[t] = make_float4(a.x + c.x, a.y + c.y, a.z + c.z, a.w + c.w);
            rB[t] += rB[t + s];
        }
        __syncthreads();
    }
    if (t == 0) {
        const float inv = 1.0f / (float)N_PTS;
        float ori_loss  = rA[0].x * inv;
        float nori_loss = rA[0].y * inv;
        float sdf_loss  = rA[0].z * inv;
        float eik_loss  = rA[0].w * inv;
        float gn_loss   = rB[0] / (3.0f * (float)N_PTS);
        float total = SDF_W * sdf_loss + EIK_W * eik_loss + ORI_W * ori_loss
                    + NEAR_ORI_W * nori_loss + GRADN_W * gn_loss;
        out[0] = total;
        out[1] = sdf_loss;
        out[2] = eik_loss;
        out[3] = ori_loss;
        out[4] = nori_loss;
        out[5] = gn_loss;
    }
}

extern "C" void kernel_launch(void* const* d_in, const int* in_sizes, int n_in,
                              void* d_out, int out_size)
{
    const float* manifold_pred    = (const float*)d_in[0];
    const float* manifold_grad    = (const float*)d_in[1];
    const float* nonmanifold_pred = (const float*)d_in[2];
    const float* near_points_pred = (const float*)d_in[3];
    const float* surface_points   = (const float*)d_in[4];
    const float* surface_normals  = (const float*)d_in[5];
    const float* off_surface_pts  = (const float*)d_in[6];
    const float* near_points      = (const float*)d_in[7];
    float* out = (float*)d_out;

    zero_kernel       <<<NCELLS / 256, 256>>>();
    build_shell_kernel<<<(BOX + 255) / 256, 256>>>();
    count_kernel      <<<N_PTS / 256, 256>>>(surface_points);
    scan_kernel       <<<1, 1024>>>();
    scatter_kernel    <<<N_PTS / 256, 256>>>(surface_points);
    grid_knn_kernel   <<<KNN_BLKS, KNN_TPB>>>(off_surface_pts, near_points);
    loss_kernel       <<<LOSS_BLK, LOSS_TPB>>>(manifold_pred, manifold_grad,
                                               nonmanifold_pred, near_points_pred,
                                               surface_points, surface_normals,
                                               off_surface_pts, near_points);
    finish_kernel     <<<1, LOSS_BLK>>>(out);
}